// round 15
// baseline (speedup 1.0000x reference)
#include <cuda_runtime.h>
#include <cuda_fp16.h>
#include <cstdint>
#include <math.h>

#define NTOK   49
#define CDIM   256
#define HEADS  8
#define HDIM   32
#define BWIN   4096
#define TOKS   (BWIN*NTOK)          // 200704 = 1568 * 128
#define KD     256                  // plain fp16
#define NITER  4                    // K/64
#define SCALE  0.17677669529663688f
#define LOG2E  1.4426950408889634f

// ---------------- scratch (device globals; no allocs) ----------------
__device__ __half g_A2[(size_t)TOKS*KD];   // attn-out  [t][256]
__device__ __half g_B1[512*KD];            // fp16(qkv_w)
__device__ __half g_B2[256*KD];            // fp16(proj_w)
// K and V tiles: [win][head] 64 tok-rows x 64B (32 fp16), swizzle key (tok>>1)&3. pads stay 0.
__device__ unsigned char g_Ks[(size_t)BWIN*HEADS*4096];
__device__ unsigned char g_Vt[(size_t)BWIN*HEADS*4096];
// Q fragments: [img][head][mtile 4][kind 2][lane 32] uint4 (pre-scaled by SCALE*LOG2E)
__device__ uint4  g_Qf[64*HEADS*4*2*32];
// bias in C-fragment layout, x LOG2E, mask folded: [head][mtile 4][ntile 7][lane 32] float4
__device__ float4 g_biasF[HEADS*4*7*32];

// ---------------- helpers ----------------
__device__ __forceinline__ uint32_t smem_u32(const void* p){
    uint32_t a;
    asm("{ .reg .u64 t; cvta.to.shared.u64 t, %1; cvt.u32.u64 %0, t; }" : "=r"(a) : "l"(p));
    return a;
}
__device__ __forceinline__ void cp_async16(uint32_t dst, const void* src){
    asm volatile("cp.async.cg.shared.global [%0], [%1], 16;" :: "r"(dst), "l"(src));
}
#define CP_COMMIT() asm volatile("cp.async.commit_group;")
#define CP_WAIT1()  asm volatile("cp.async.wait_group 1;")
#define CP_WAIT0()  asm volatile("cp.async.wait_group 0;")

__device__ __forceinline__ void ldmx4(uint32_t* r, uint32_t addr){
    asm volatile("ldmatrix.sync.aligned.m8n8.x4.shared.b16 {%0,%1,%2,%3}, [%4];"
        : "=r"(r[0]), "=r"(r[1]), "=r"(r[2]), "=r"(r[3]) : "r"(addr));
}
__device__ __forceinline__ void ldmx4t(uint32_t* r, uint32_t addr){
    asm volatile("ldmatrix.sync.aligned.m8n8.x4.trans.shared.b16 {%0,%1,%2,%3}, [%4];"
        : "=r"(r[0]), "=r"(r[1]), "=r"(r[2]), "=r"(r[3]) : "r"(addr));
}
__device__ __forceinline__ void mma16816(float* c, const uint32_t* a, const uint32_t* b){
    asm volatile("mma.sync.aligned.m16n8k16.row.col.f32.f16.f16.f32 "
        "{%0,%1,%2,%3}, {%4,%5,%6,%7}, {%8,%9}, {%0,%1,%2,%3};"
        : "+f"(c[0]), "+f"(c[1]), "+f"(c[2]), "+f"(c[3])
        : "r"(a[0]), "r"(a[1]), "r"(a[2]), "r"(a[3]), "r"(b[0]), "r"(b[1]));
}
__device__ __forceinline__ uint32_t pk2f(float a, float b){
    __half2 h = __floats2half2_rn(a, b);
    return *reinterpret_cast<uint32_t*>(&h);
}
__device__ __forceinline__ int rpi(int r, int c){
    int ai = r/7, aj = r%7, bi = c/7, bj = c%7;
    return (ai - bi + 6)*13 + (aj - bj + 6);
}

// ------- prep: weights fp16, bias fragments, Q fragments (small) -----------
__global__ void prep_k(const float* __restrict__ qkv_w,
                       const float* __restrict__ proj_w,
                       const float* __restrict__ rbt,
                       const float* __restrict__ qg)
{
    int idx = blockIdx.x * 256 + threadIdx.x;   // 512*256 = 131072
    if (idx < 512*256) g_B1[idx] = __float2half_rn(qkv_w[idx]);
    if (idx < 256*256) g_B2[idx] = __float2half_rn(proj_w[idx]);
    if (idx < HEADS*4*7*32) {
        int lane = idx & 31;
        int nt = (idx >> 5) % 7;
        int mt = (idx >> 5) / 7 % 4;
        int h  = idx / (32*7*4);
        int r0 = mt*16 + (lane>>2), r1 = r0 + 8;
        int c0 = nt*8 + 2*(lane&3), c1 = c0 + 1;
        float4 v;
        v.x = (r0 < 49 && c0 < 49) ? rbt[rpi(r0,c0)*HEADS + h]*LOG2E : -1e30f;
        v.y = (r0 < 49 && c1 < 49) ? rbt[rpi(r0,c1)*HEADS + h]*LOG2E : -1e30f;
        v.z = (r1 < 49 && c0 < 49) ? rbt[rpi(r1,c0)*HEADS + h]*LOG2E : -1e30f;
        v.w = (r1 < 49 && c1 < 49) ? rbt[rpi(r1,c1)*HEADS + h]*LOG2E : -1e30f;
        g_biasF[idx] = v;
    }
    {   // Q fragments: 64*8*4*2*32 = 131072
        int lane = idx & 31;
        int kind = (idx >> 5) & 1;
        int mt   = (idx >> 6) & 3;
        int h    = (idx >> 8) & 7;
        int img  = idx >> 11;
        int r = mt*16 + (lane>>2);
        int c2 = 2*(lane&3);
        int db = kind * 16;
        const float qs = SCALE * LOG2E;
        auto qget = [&](int rr, int d) -> float {
            if (rr >= 49) return 0.f;
            return qg[(((size_t)img*HEADS + h)*NTOK + rr)*HDIM + d] * qs;
        };
        uint4 o;
        o.x = pk2f(qget(r,   db+c2),   qget(r,   db+c2+1));
        o.y = pk2f(qget(r+8, db+c2),   qget(r+8, db+c2+1));
        o.z = pk2f(qget(r,   db+c2+8), qget(r,   db+c2+9));
        o.w = pk2f(qget(r+8, db+c2+8), qget(r+8, db+c2+9));
        g_Qf[idx] = o;
    }
}

// ------- gemm1: KV = fp16(x) @ B1^T, fused fp32->fp16 A loader -------------
// SMEM: [0,64K) B resident (4 k-chunks x 16KB) ; [64K, 64K+2*16K) A ping-pong
#define GA_OFF 65536
#define G1SMEM (65536 + 2*16384)   // 96 KB

__global__ void __launch_bounds__(256, 2)
gemm1_k(const float* __restrict__ x, const float* __restrict__ bias)
{
    extern __shared__ char sm[];
    const int tid = threadIdx.x;
    const int n0 = blockIdx.x * 128;
    const int m0 = blockIdx.y * 128;
    const uint32_t sb = smem_u32(sm);

    // B resident: load full 128x256 tile once (64KB)
    {
        const char* Bbase = (const char*)g_B1 + (size_t)n0*KD*2;
        #pragma unroll
        for (int u = 0; u < 16; u++) {
            int idx = tid + u*256;
            int kc = idx >> 10;
            int rem = idx & 1023;
            int r = rem >> 3, c16 = rem & 7;
            uint32_t dst = (uint32_t)(kc*16384 + r*128 + ((c16 ^ (r & 7))*16));
            cp_async16(sb + dst, Bbase + (size_t)r*(KD*2) + kc*128 + c16*16);
        }
        CP_COMMIT();
    }

    // A loader: thread -> (row, half-row); LDG fp32, cvt, STS fp16 swizzled
    const int ar = tid >> 1;        // 0..127
    const int fh = tid & 1;         // 32-float half
    uint32_t bufc[16];
    auto ldg_cvt = [&](int i){
        const float4* src = (const float4*)(x + ((size_t)(m0 + ar))*CDIM + i*64 + fh*32);
        #pragma unroll
        for (int j = 0; j < 8; j++) {
            float4 v = __ldg(src + j);
            bufc[2*j]   = pk2f(v.x, v.y);
            bufc[2*j+1] = pk2f(v.z, v.w);
        }
    };
    auto sts_a = [&](int i){
        char* base = sm + GA_OFF + (i & 1)*16384 + ar*128;
        #pragma unroll
        for (int j = 0; j < 4; j++) {
            int c16 = fh*4 + j;
            *(uint4*)(base + ((c16 ^ (ar & 7))*16))
                = make_uint4(bufc[4*j], bufc[4*j+1], bufc[4*j+2], bufc[4*j+3]);
        }
    };

    const int w = tid >> 5, lane = tid & 31;
    const int wm = w >> 1, wn = w & 1;
    const int aRow = wm*32 + (lane & 15);
    const int aC16 = (lane >> 4);
    const int bRow = wn*64 + (lane & 7) + ((lane >> 4) << 3);
    const int bC16 = (lane >> 3) & 1;
    const int lc2 = 2*(lane & 3);

    float acc[2][8][4];
    #pragma unroll
    for (int mt = 0; mt < 2; mt++)
        #pragma unroll
        for (int nt = 0; nt < 8; nt++)
            #pragma unroll
            for (int q = 0; q < 4; q++) acc[mt][nt][q] = 0.f;

    ldg_cvt(0);
    sts_a(0);
    ldg_cvt(1);
    CP_WAIT0();                       // B resident complete
    for (int i = 0; i < NITER; i++) {
        __syncthreads();              // stage i visible; stage (i+1)&1 free
        if (i + 1 < NITER) sts_a(i + 1);
        if (i + 2 < NITER) ldg_cvt(i + 2);
        const uint32_t sa  = sb + GA_OFF + (i & 1)*16384;
        const uint32_t sbB = sb + i*16384;          // resident B, k-chunk i
        uint32_t af[4][2][4];
        #pragma unroll
        for (int kk = 0; kk < 4; kk++)
            #pragma unroll
            for (int mt = 0; mt < 2; mt++) {
                int r = aRow + mt*16, c = kk*2 + aC16;
                ldmx4(af[kk][mt], sa + r*128 + ((c ^ (r & 7))*16));
            }
        #pragma unroll
        for (int kk = 0; kk < 4; kk++) {
            #pragma unroll
            for (int np = 0; np < 4; np++) {
                uint32_t bf[4];
                int r = bRow + np*16, c = kk*2 + bC16;
                ldmx4(bf, sbB + r*128 + ((c ^ (r & 7))*16));
                #pragma unroll
                for (int mt = 0; mt < 2; mt++) {
                    mma16816(acc[mt][np*2+0], af[kk][mt], bf+0);
                    mma16816(acc[mt][np*2+1], af[kk][mt], bf+2);
                }
            }
        }
    }

    // unified K/V epilogue: both hi-only tok-major 64B-row tiles, same swizzle
    const bool isK = (n0 + wn*64) < 256;
    char* arr = isK ? (char*)g_Ks : (char*)g_Vt;
    #pragma unroll
    for (int mt = 0; mt < 2; mt++) {
        int rowb = m0 + wm*32 + mt*16 + (lane >> 2);
        #pragma unroll
        for (int rr = 0; rr < 2; rr++) {
            int r = rowb + rr*8;
            int win = r / 49, tok = r - win*49;
            int key = (tok >> 1) & 3;
            char* base = arr + (size_t)win*(HEADS*4096) + (size_t)tok*64;
            #pragma unroll
            for (int nt = 0; nt < 8; nt++) {
                int gc = n0 + wn*64 + nt*8 + lc2;
                float v0 = acc[mt][nt][rr*2]   + __ldg(bias + gc);
                float v1 = acc[mt][nt][rr*2+1] + __ldg(bias + gc + 1);
                int c = gc & 255, head = c >> 5, d = c & 31;
                char* tb = base + head*4096;
                int chunk = d >> 3, inb = (2*d) & 15;
                *(uint32_t*)(tb + ((chunk ^ key)*16) + inb) = pk2f(v0, v1);
            }
        }
    }
}

// ------- gemm2: out = A2 @ B2^T + b, B-resident, cp.async A ---------------
#define G2SMEM (65536 + 3*16384)   // 112 KB

__global__ void __launch_bounds__(256, 2)
gemm2_k(const float* __restrict__ bias, float* __restrict__ extC)
{
    extern __shared__ char sm[];
    const int tid = threadIdx.x;
    const int n0 = blockIdx.x * 128;
    const int m0 = blockIdx.y * 128;
    const uint32_t sb = smem_u32(sm);

    {
        const char* Bbase = (const char*)g_B2 + (size_t)n0*KD*2;
        #pragma unroll
        for (int u = 0; u < 16; u++) {
            int idx = tid + u*256;
            int kc = idx >> 10;
            int rem = idx & 1023;
            int r = rem >> 3, c16 = rem & 7;
            uint32_t dst = (uint32_t)(kc*16384 + r*128 + ((c16 ^ (r & 7))*16));
            cp_async16(sb + dst, Bbase + (size_t)r*(KD*2) + kc*128 + c16*16);
        }
        CP_COMMIT();
    }

    auto load_a = [&](int i, int s){
        const char* Abase = (const char*)g_A2 + ((size_t)m0*KD + (size_t)i*64)*2;
        uint32_t sa = sb + GA_OFF + s*16384;
        #pragma unroll
        for (int u = 0; u < 4; u++) {
            int idx = tid + u*256;
            int r = idx >> 3, c16 = idx & 7;
            uint32_t dst = (uint32_t)(r*128 + ((c16 ^ (r & 7))*16));
            cp_async16(sa + dst, Abase + (size_t)r*(KD*2) + c16*16);
        }
        CP_COMMIT();
    };

    const int w = tid >> 5, lane = tid & 31;
    const int wm = w >> 1, wn = w & 1;
    const int aRow = wm*32 + (lane & 15);
    const int aC16 = (lane >> 4);
    const int bRow = wn*64 + (lane & 7) + ((lane >> 4) << 3);
    const int bC16 = (lane >> 3) & 1;
    const int lc2 = 2*(lane & 3);

    float acc[2][8][4];
    #pragma unroll
    for (int mt = 0; mt < 2; mt++)
        #pragma unroll
        for (int nt = 0; nt < 8; nt++)
            #pragma unroll
            for (int q = 0; q < 4; q++) acc[mt][nt][q] = 0.f;

    load_a(0, 0);
    load_a(1, 1);
    int s = 0;
    for (int i = 0; i < NITER; i++) {
        if (i < NITER-1) { CP_WAIT1(); } else { CP_WAIT0(); }
        __syncthreads();
        if (i + 2 < NITER) {
            int s2 = s + 2; if (s2 >= 3) s2 -= 3;
            load_a(i + 2, s2);
        }
        const uint32_t sa  = sb + GA_OFF + s*16384;
        const uint32_t sbB = sb + i*16384;
        uint32_t af[4][2][4];
        #pragma unroll
        for (int kk = 0; kk < 4; kk++)
            #pragma unroll
            for (int mt = 0; mt < 2; mt++) {
                int r = aRow + mt*16, c = kk*2 + aC16;
                ldmx4(af[kk][mt], sa + r*128 + ((c ^ (r & 7))*16));
            }
        #pragma unroll
        for (int kk = 0; kk < 4; kk++) {
            #pragma unroll
            for (int np = 0; np < 4; np++) {
                uint32_t bf[4];
                int r = bRow + np*16, c = kk*2 + bC16;
                ldmx4(bf, sbB + r*128 + ((c ^ (r & 7))*16));
                #pragma unroll
                for (int mt = 0; mt < 2; mt++) {
                    mma16816(acc[mt][np*2+0], af[kk][mt], bf+0);
                    mma16816(acc[mt][np*2+1], af[kk][mt], bf+2);
                }
            }
        }
        if (++s >= 3) s -= 3;
    }

    #pragma unroll
    for (int nt = 0; nt < 8; nt++) {
        int col = n0 + wn*64 + nt*8 + lc2;
        float bx = __ldg(bias + col), by = __ldg(bias + col + 1);
        #pragma unroll
        for (int mt = 0; mt < 2; mt++) {
            int row = m0 + wm*32 + mt*16 + (lane >> 2);
            float2 v0 = make_float2(acc[mt][nt][0] + bx, acc[mt][nt][1] + by);
            float2 v1 = make_float2(acc[mt][nt][2] + bx, acc[mt][nt][3] + by);
            *(float2*)(extC + (size_t)row*256 + col)       = v0;
            *(float2*)(extC + (size_t)(row+8)*256 + col)   = v1;
        }
    }
}

// ---------------- tensor-core attention (fp16, exp2 softmax, no max-pass) ---
#define ASMEM (32768 + 32768)   // K 32KB + V 32KB = 64KB
__global__ void __launch_bounds__(256, 3)
attn_k()
{
    extern __shared__ char sm[];
    const int tid = threadIdx.x, b = blockIdx.x;
    const uint32_t sb = smem_u32(sm);

    {   // zero-fill pad rows 49..63 of every head tile (K and V buffers)
        for (int u = tid; u < 960; u += 256) {
            int buf = u / 480, i = u - buf*480;
            int head = i / 60, rem = i - head*60;
            uint32_t off = (uint32_t)(buf*32768 + head*4096 + (49 + (rem>>2))*64 + (rem&3)*16);
            *(uint4*)(sm + off) = make_uint4(0,0,0,0);
        }
        // stage K rows 0..48 (group 0), then V rows 0..48 (group 1)
        const char* srcK = (const char*)g_Ks + (size_t)b*32768;
        const char* srcV = (const char*)g_Vt + (size_t)b*32768;
        #pragma unroll
        for (int u = 0; u < 7; u++) {
            int i = tid + u*256;
            if (i < 1568) {
                int head = i / 196, rem = i - head*196;
                uint32_t off = (uint32_t)(head*4096 + (rem>>2)*64 + (rem&3)*16);
                cp_async16(sb + off, srcK + off);
            }
        }
        CP_COMMIT();
        #pragma unroll
        for (int u = 0; u < 7; u++) {
            int i = tid + u*256;
            if (i < 1568) {
                int head = i / 196, rem = i - head*196;
                uint32_t off = (uint32_t)(head*4096 + (rem>>2)*64 + (rem&3)*16);
                cp_async16(sb + 32768 + off, srcV + off);
            }
        }
        CP_COMMIT();
        CP_WAIT1();   // K arrived; V still in flight
    }
    __syncthreads();

    const int h = tid >> 5, lane = tid & 31;
    const int img = b >> 6;
    const uint32_t Kt = sb + h*4096;
    const uint32_t Vt = sb + 32768 + h*4096;
    const int lr = lane >> 2, lc2 = 2*(lane & 3);
    const int brow = (lane & 7) + ((lane >> 4) << 3);
    const int bch  = (lane >> 3) & 1;
    const int vrow = lane & 15;
    const int vch  = lane >> 4;

    const uint4*  qf = g_Qf    + ((size_t)(img*HEADS + h)*8)*32 + lane;
    const float4* bf = g_biasF + ((size_t)h*4*7)*32 + lane;

    for (int mt = 0; mt < 4; mt++) {
        uint32_t af[2][4];
        #pragma unroll
        for (int kd = 0; kd < 2; kd++) {
            uint4 v = __ldg(qf + (mt*2 + kd)*32);
            af[kd][0]=v.x; af[kd][1]=v.y; af[kd][2]=v.z; af[kd][3]=v.w;
        }
        float s[8][4];
        #pragma unroll
        for (int nt = 0; nt < 8; nt++)
            #pragma unroll
            for (int j = 0; j < 4; j++) s[nt][j] = 0.f;

        // QK^T in log2 domain (Q pre-scaled by SCALE*log2e)
        #pragma unroll
        for (int np = 0; np < 4; np++) {
            uint32_t kb[2][4];
            int row = np*16 + brow;
            int key = (row >> 1) & 3;
            #pragma unroll
            for (int ch = 0; ch < 2; ch++) {
                int chunk = ch*2 + bch;
                ldmx4(kb[ch], Kt + row*64 + ((chunk ^ key)*16));
            }
            float* s0 = s[2*np]; float* s1 = s[2*np+1];
            mma16816(s0, af[0], kb[0]+0); mma16816(s1, af[0], kb[0]+2);
            mma16816(s0, af[1], kb[1]+0); mma16816(s1, af[1], kb[1]+2);
        }

        // softmax (no max-pass: scores bounded); p = exp2(s + bias2)
        float den0 = 0.f, den1 = 0.f;
        #pragma unroll
        for (int nt = 0; nt < 7; nt++) {
            float4 t = __ldg(bf + (mt*7 + nt)*32);
            s[nt][0] = exp2f(s[nt][0] + t.x); den0 += s[nt][0];
            s[nt][1] = exp2f(s[nt][1] + t.y); den0 += s[nt][1];
            s[nt][2] = exp2f(s[nt][2] + t.z); den1 += s[nt][2];
            s[nt][3] = exp2f(s[nt][3] + t.w); den1 += s[nt][3];
        }
        den0 += __shfl_xor_sync(0xFFFFFFFF, den0, 1);
        den0 += __shfl_xor_sync(0xFFFFFFFF, den0, 2);
        den1 += __shfl_xor_sync(0xFFFFFFFF, den1, 1);
        den1 += __shfl_xor_sync(0xFFFFFFFF, den1, 2);
        float rinv0 = 1.f / den0, rinv1 = 1.f / den1;

        // P -> A fragments (fp16, packed cvt)
        uint32_t ph[4][4];
        #pragma unroll
        for (int ks = 0; ks < 4; ks++) {
            #pragma unroll
            for (int half_ = 0; half_ < 2; half_++) {
                int nt = 2*ks + half_;
                if (nt < 7) {
                    ph[ks][half_*2+0] = pk2f(s[nt][0], s[nt][1]);
                    ph[ks][half_*2+1] = pk2f(s[nt][2], s[nt][3]);
                } else {
                    ph[ks][half_*2] = 0; ph[ks][half_*2+1] = 0;
                }
            }
        }

        // before first PV, make sure V staging landed
        if (mt == 0) { CP_WAIT0(); __syncthreads(); }

        // PV: p x v, V via ldmatrix.trans from tok-major tiles
        float o[4][4];
        #pragma unroll
        for (int nt = 0; nt < 4; nt++)
            #pragma unroll
            for (int j = 0; j < 4; j++) o[nt][j] = 0.f;
        #pragma unroll
        for (int ks = 0; ks < 4; ks++) {
            int row = ks*16 + vrow;
            int key = (row >> 1) & 3;
            #pragma unroll
            for (int nh = 0; nh < 2; nh++) {
                uint32_t vh[4];
                int chunk = nh*2 + vch;
                ldmx4t(vh, Vt + row*64 + ((chunk ^ key)*16));
                mma16816(o[2*nh+0], ph[ks], vh+0);
                mma16816(o[2*nh+1], ph[ks], vh+2);
            }
        }

        // store to g_A2 (fp16, [t][256]), packed cvt
        int r0 = mt*16 + lr, r1 = r0 + 8;
        if (r0 < 49) {
            __half* dst = g_A2 + ((size_t)b*NTOK + r0)*KD;
            #pragma unroll
            for (int nt = 0; nt < 4; nt++) {
                int gc = h*HDIM + nt*8 + lc2;
                *(uint32_t*)(dst + gc) = pk2f(o[nt][0]*rinv0, o[nt][1]*rinv0);
            }
        }
        if (r1 < 49) {
            __half* dst = g_A2 + ((size_t)b*NTOK + r1)*KD;
            #pragma unroll
            for (int nt = 0; nt < 4; nt++) {
                int gc = h*HDIM + nt*8 + lc2;
                *(uint32_t*)(dst + gc) = pk2f(o[nt][2]*rinv1, o[nt][3]*rinv1);
            }
        }
    }
}

// ---------------- launch ----------------
extern "C" void kernel_launch(void* const* d_in, const int* in_sizes, int n_in,
                              void* d_out, int out_size)
{
    const float* x      = (const float*)d_in[0];
    const float* qg     = (const float*)d_in[1];
    const float* qkv_w  = (const float*)d_in[2];
    const float* qkv_b  = (const float*)d_in[3];
    const float* proj_w = (const float*)d_in[4];
    const float* proj_b = (const float*)d_in[5];
    const float* rbt    = (const float*)d_in[6];
    float* out = (float*)d_out;
    (void)in_sizes; (void)n_in; (void)out_size;

    cudaFuncSetAttribute(gemm1_k, cudaFuncAttributeMaxDynamicSharedMemorySize, G1SMEM);
    cudaFuncSetAttribute(gemm2_k, cudaFuncAttributeMaxDynamicSharedMemorySize, G2SMEM);
    cudaFuncSetAttribute(attn_k,  cudaFuncAttributeMaxDynamicSharedMemorySize, ASMEM);

    prep_k<<<512, 256>>>(qkv_w, proj_w, rbt, qg);
    {
        dim3 g1(4, TOKS/128);
        gemm1_k<<<g1, 256, G1SMEM>>>(x, qkv_b);
    }
    attn_k<<<BWIN, 256, ASMEM>>>();
    {
        dim3 g2(2, TOKS/128);
        gemm2_k<<<g2, 256, G2SMEM>>>(proj_b, out);
    }
}

// round 16
// speedup vs baseline: 1.3880x; 1.3880x over previous
#include <cuda_runtime.h>
#include <cuda_fp16.h>
#include <cstdint>
#include <math.h>

#define NTOK   49
#define CDIM   256
#define HEADS  8
#define HDIM   32
#define BWIN   4096
#define TOKS   (BWIN*NTOK)          // 200704 = 1568 * 128
#define KD     256                  // plain fp16
#define NITER  4                    // K/64
#define SCALE  0.17677669529663688f
#define LOG2E  1.4426950408889634f

// ---------------- scratch (device globals; no allocs) ----------------
__device__ __half g_A1[(size_t)TOKS*KD];   // fp16(x)   [t][256]
__device__ __half g_A2[(size_t)TOKS*KD];   // attn-out  [t][256]
__device__ __half g_B1[512*KD];            // fp16(qkv_w)
__device__ __half g_B2[256*KD];            // fp16(proj_w)
// K and V tiles: [win][head] 64 tok-rows x 64B (32 fp16), swizzle key (tok>>1)&3. pads stay 0.
__device__ unsigned char g_Ks[(size_t)BWIN*HEADS*4096];
__device__ unsigned char g_Vt[(size_t)BWIN*HEADS*4096];
// Q fragments: [img][head][mtile 4][kind 2][lane 32] uint4 (pre-scaled by SCALE*LOG2E)
__device__ uint4  g_Qf[64*HEADS*4*2*32];
// bias in C-fragment layout, x LOG2E, mask folded: [head][mtile 4][ntile 7][lane 32] float4
__device__ float4 g_biasF[HEADS*4*7*32];

// ---------------- helpers ----------------
__device__ __forceinline__ uint32_t smem_u32(const void* p){
    uint32_t a;
    asm("{ .reg .u64 t; cvta.to.shared.u64 t, %1; cvt.u32.u64 %0, t; }" : "=r"(a) : "l"(p));
    return a;
}
__device__ __forceinline__ void cp_async16(uint32_t dst, const void* src){
    asm volatile("cp.async.cg.shared.global [%0], [%1], 16;" :: "r"(dst), "l"(src));
}
#define CP_COMMIT() asm volatile("cp.async.commit_group;")
#define CP_WAIT1()  asm volatile("cp.async.wait_group 1;")
#define CP_WAIT0()  asm volatile("cp.async.wait_group 0;")

__device__ __forceinline__ void ldmx4(uint32_t* r, uint32_t addr){
    asm volatile("ldmatrix.sync.aligned.m8n8.x4.shared.b16 {%0,%1,%2,%3}, [%4];"
        : "=r"(r[0]), "=r"(r[1]), "=r"(r[2]), "=r"(r[3]) : "r"(addr));
}
__device__ __forceinline__ void ldmx4t(uint32_t* r, uint32_t addr){
    asm volatile("ldmatrix.sync.aligned.m8n8.x4.trans.shared.b16 {%0,%1,%2,%3}, [%4];"
        : "=r"(r[0]), "=r"(r[1]), "=r"(r[2]), "=r"(r[3]) : "r"(addr));
}
__device__ __forceinline__ void mma16816(float* c, const uint32_t* a, const uint32_t* b){
    asm volatile("mma.sync.aligned.m16n8k16.row.col.f32.f16.f16.f32 "
        "{%0,%1,%2,%3}, {%4,%5,%6,%7}, {%8,%9}, {%0,%1,%2,%3};"
        : "+f"(c[0]), "+f"(c[1]), "+f"(c[2]), "+f"(c[3])
        : "r"(a[0]), "r"(a[1]), "r"(a[2]), "r"(a[3]), "r"(b[0]), "r"(b[1]));
}
__device__ __forceinline__ uint32_t pk2f(float a, float b){
    __half2 h = __floats2half2_rn(a, b);
    return *reinterpret_cast<uint32_t*>(&h);
}
__device__ __forceinline__ int rpi(int r, int c){
    int ai = r/7, aj = r%7, bi = c/7, bj = c%7;
    return (ai - bi + 6)*13 + (aj - bj + 6);
}

// ------- prep (weights, bias, Q frags) + conv_x merged, grid 4096x256 -------
__global__ void prep_conv(const float* __restrict__ qkv_w,
                          const float* __restrict__ proj_w,
                          const float* __restrict__ rbt,
                          const float* __restrict__ qg,
                          const float* __restrict__ x)
{
    int idx = blockIdx.x * 256 + threadIdx.x;
    if (idx < 512*256) g_B1[idx] = __float2half_rn(qkv_w[idx]);
    if (idx < 256*256) g_B2[idx] = __float2half_rn(proj_w[idx]);
    if (idx < HEADS*4*7*32) {
        int lane = idx & 31;
        int nt = (idx >> 5) % 7;
        int mt = (idx >> 5) / 7 % 4;
        int h  = idx / (32*7*4);
        int r0 = mt*16 + (lane>>2), r1 = r0 + 8;
        int c0 = nt*8 + 2*(lane&3), c1 = c0 + 1;
        float4 v;
        v.x = (r0 < 49 && c0 < 49) ? rbt[rpi(r0,c0)*HEADS + h]*LOG2E : -1e30f;
        v.y = (r0 < 49 && c1 < 49) ? rbt[rpi(r0,c1)*HEADS + h]*LOG2E : -1e30f;
        v.z = (r1 < 49 && c0 < 49) ? rbt[rpi(r1,c0)*HEADS + h]*LOG2E : -1e30f;
        v.w = (r1 < 49 && c1 < 49) ? rbt[rpi(r1,c1)*HEADS + h]*LOG2E : -1e30f;
        g_biasF[idx] = v;
    }
    if (idx < 64*HEADS*4*2*32) {   // Q fragments, pre-scaled by SCALE*LOG2E
        int lane = idx & 31;
        int kind = (idx >> 5) & 1;
        int mt   = (idx >> 6) & 3;
        int h    = (idx >> 8) & 7;
        int img  = idx >> 11;
        int r = mt*16 + (lane>>2);
        int c2 = 2*(lane&3);
        int db = kind * 16;
        const float qs = SCALE * LOG2E;
        auto qget = [&](int rr, int d) -> float {
            if (rr >= 49) return 0.f;
            return qg[(((size_t)img*HEADS + h)*NTOK + rr)*HDIM + d] * qs;
        };
        uint4 o;
        o.x = pk2f(qget(r,   db+c2),   qget(r,   db+c2+1));
        o.y = pk2f(qget(r+8, db+c2),   qget(r+8, db+c2+1));
        o.z = pk2f(qget(r,   db+c2+8), qget(r,   db+c2+9));
        o.w = pk2f(qget(r+8, db+c2+8), qget(r+8, db+c2+9));
        g_Qf[idx] = o;
    }
    // conv_x: grid-stride over TOKS*64 float4s
    {
        const float4* x4 = (const float4*)x;
        int stride = gridDim.x * 256;
        for (int i = idx; i < TOKS*64; i += stride) {
            float4 v = __ldg(x4 + i);
            *(uint2*)(g_A1 + (size_t)i*4) = make_uint2(pk2f(v.x, v.y), pk2f(v.z, v.w));
        }
    }
}

// ------- mma.sync fp16 GEMM, B-resident: C[128,128] per CTA, K=256 ---------
// SMEM: [0,64K) B full tile (4 k-chunks x 16KB) ; [64K, 64K+3*16K) A stages
#define GA_OFF 65536
#define GSMEM  (65536 + 3*16384)   // 112 KB

template<int NOUT>
__global__ void __launch_bounds__(256, 2)
gemm_k(const float* __restrict__ bias, float* __restrict__ extC)
{
    extern __shared__ char sm[];
    const __half* Ag = (NOUT == 512) ? g_A1 : g_A2;
    const __half* Bg = (NOUT == 512) ? g_B1 : g_B2;

    const int tid = threadIdx.x;
    const int n0 = blockIdx.x * 128;
    const int m0 = blockIdx.y * 128;
    const uint32_t sb = smem_u32(sm);

    // B: load the whole 128x256 tile once (64KB, 4096 16B chunks)
    {
        const char* Bbase = (const char*)Bg + (size_t)n0*KD*2;
        #pragma unroll
        for (int u = 0; u < 16; u++) {
            int idx = tid + u*256;          // 0..4095
            int kc = idx >> 10;             // k-chunk 0..3
            int rem = idx & 1023;
            int r = rem >> 3, c16 = rem & 7;
            uint32_t dst = (uint32_t)(kc*16384 + r*128 + ((c16 ^ (r & 7))*16));
            cp_async16(sb + dst, Bbase + (size_t)r*(KD*2) + kc*128 + c16*16);
        }
        CP_COMMIT();
    }

    auto load_a = [&](int i, int s){
        const char* Abase = (const char*)Ag + ((size_t)m0*KD + (size_t)i*64)*2;
        uint32_t sa = sb + GA_OFF + s*16384;
        #pragma unroll
        for (int u = 0; u < 4; u++) {
            int idx = tid + u*256;
            int r = idx >> 3, c16 = idx & 7;
            uint32_t dst = (uint32_t)(r*128 + ((c16 ^ (r & 7))*16));
            cp_async16(sa + dst, Abase + (size_t)r*(KD*2) + c16*16);
        }
        CP_COMMIT();
    };

    const int w = tid >> 5, lane = tid & 31;
    const int wm = w >> 1, wn = w & 1;
    const int aRow = wm*32 + (lane & 15);
    const int aC16 = (lane >> 4);
    const int bRow = wn*64 + (lane & 7) + ((lane >> 4) << 3);
    const int bC16 = (lane >> 3) & 1;
    const int lc2 = 2*(lane & 3);

    float acc[2][8][4];
    #pragma unroll
    for (int mt = 0; mt < 2; mt++)
        #pragma unroll
        for (int nt = 0; nt < 8; nt++)
            #pragma unroll
            for (int q = 0; q < 4; q++) acc[mt][nt][q] = 0.f;

    load_a(0, 0);
    load_a(1, 1);
    int s = 0;
    for (int i = 0; i < NITER; i++) {
        // pending groups: i=0:{B,A0,A1} wait1->B,A0 ; i=1:{A1,A2} wait1->A1 ; ...
        if (i < NITER-1) { CP_WAIT1(); } else { CP_WAIT0(); }
        __syncthreads();
        if (i + 2 < NITER) {
            int s2 = s + 2; if (s2 >= 3) s2 -= 3;
            load_a(i + 2, s2);
        }
        const uint32_t sa  = sb + GA_OFF + s*16384;
        const uint32_t sbB = sb + i*16384;          // resident B, k-chunk i
        uint32_t af[4][2][4];
        #pragma unroll
        for (int kk = 0; kk < 4; kk++)
            #pragma unroll
            for (int mt = 0; mt < 2; mt++) {
                int r = aRow + mt*16, c = kk*2 + aC16;
                ldmx4(af[kk][mt], sa + r*128 + ((c ^ (r & 7))*16));
            }
        #pragma unroll
        for (int kk = 0; kk < 4; kk++) {
            #pragma unroll
            for (int np = 0; np < 4; np++) {
                uint32_t bf[4];
                int r = bRow + np*16, c = kk*2 + bC16;
                ldmx4(bf, sbB + r*128 + ((c ^ (r & 7))*16));
                #pragma unroll
                for (int mt = 0; mt < 2; mt++) {
                    mma16816(acc[mt][np*2+0], af[kk][mt], bf+0);
                    mma16816(acc[mt][np*2+1], af[kk][mt], bf+2);
                }
            }
        }
        if (++s >= 3) s -= 3;
    }

    if (NOUT == 256) {
        #pragma unroll
        for (int nt = 0; nt < 8; nt++) {
            int col = n0 + wn*64 + nt*8 + lc2;
            float bx = __ldg(bias + col), by = __ldg(bias + col + 1);
            #pragma unroll
            for (int mt = 0; mt < 2; mt++) {
                int row = m0 + wm*32 + mt*16 + (lane >> 2);
                float2 v0 = make_float2(acc[mt][nt][0] + bx, acc[mt][nt][1] + by);
                float2 v1 = make_float2(acc[mt][nt][2] + bx, acc[mt][nt][3] + by);
                *(float2*)(extC + (size_t)row*NOUT + col)       = v0;
                *(float2*)(extC + (size_t)(row+8)*NOUT + col)   = v1;
            }
        }
    } else {
        // unified K/V epilogue: both hi-only tok-major 64B-row tiles, same swizzle
        const bool isK = (n0 + wn*64) < 256;
        char* arr = isK ? (char*)g_Ks : (char*)g_Vt;
        #pragma unroll
        for (int mt = 0; mt < 2; mt++) {
            int rowb = m0 + wm*32 + mt*16 + (lane >> 2);
            #pragma unroll
            for (int rr = 0; rr < 2; rr++) {
                int r = rowb + rr*8;
                int win = r / 49, tok = r - win*49;
                int key = (tok >> 1) & 3;
                char* base = arr + (size_t)win*(HEADS*4096) + (size_t)tok*64;
                #pragma unroll
                for (int nt = 0; nt < 8; nt++) {
                    int gc = n0 + wn*64 + nt*8 + lc2;
                    float v0 = acc[mt][nt][rr*2]   + __ldg(bias + gc);
                    float v1 = acc[mt][nt][rr*2+1] + __ldg(bias + gc + 1);
                    int c = gc & 255, head = c >> 5, d = c & 31;
                    char* tb = base + head*4096;
                    int chunk = d >> 3, inb = (2*d) & 15;
                    *(uint32_t*)(tb + ((chunk ^ key)*16) + inb) = pk2f(v0, v1);
                }
            }
        }
    }
}

// ---------------- tensor-core attention (fp16, exp2 softmax, no max-pass) ---
#define ASMEM (32768 + 32768)   // K 32KB + V 32KB = 64KB
__global__ void __launch_bounds__(256, 3)
attn_k()
{
    extern __shared__ char sm[];
    const int tid = threadIdx.x, b = blockIdx.x;
    const uint32_t sb = smem_u32(sm);

    {   // zero-fill pad rows 49..63 of every head tile (K and V buffers)
        for (int u = tid; u < 960; u += 256) {
            int buf = u / 480, i = u - buf*480;
            int head = i / 60, rem = i - head*60;
            uint32_t off = (uint32_t)(buf*32768 + head*4096 + (49 + (rem>>2))*64 + (rem&3)*16);
            *(uint4*)(sm + off) = make_uint4(0,0,0,0);
        }
        // stage K rows 0..48 (group 0), then V rows 0..48 (group 1)
        const char* srcK = (const char*)g_Ks + (size_t)b*32768;
        const char* srcV = (const char*)g_Vt + (size_t)b*32768;
        #pragma unroll
        for (int u = 0; u < 7; u++) {
            int i = tid + u*256;
            if (i < 1568) {
                int head = i / 196, rem = i - head*196;
                uint32_t off = (uint32_t)(head*4096 + (rem>>2)*64 + (rem&3)*16);
                cp_async16(sb + off, srcK + off);
            }
        }
        CP_COMMIT();
        #pragma unroll
        for (int u = 0; u < 7; u++) {
            int i = tid + u*256;
            if (i < 1568) {
                int head = i / 196, rem = i - head*196;
                uint32_t off = (uint32_t)(head*4096 + (rem>>2)*64 + (rem&3)*16);
                cp_async16(sb + 32768 + off, srcV + off);
            }
        }
        CP_COMMIT();
        CP_WAIT1();   // K arrived; V still in flight
    }
    __syncthreads();

    const int h = tid >> 5, lane = tid & 31;
    const int img = b >> 6;
    const uint32_t Kt = sb + h*4096;
    const uint32_t Vt = sb + 32768 + h*4096;
    const int lr = lane >> 2, lc2 = 2*(lane & 3);
    const int brow = (lane & 7) + ((lane >> 4) << 3);
    const int bch  = (lane >> 3) & 1;
    const int vrow = lane & 15;
    const int vch  = lane >> 4;

    const uint4*  qf = g_Qf    + ((size_t)(img*HEADS + h)*8)*32 + lane;
    const float4* bf = g_biasF + ((size_t)h*4*7)*32 + lane;

    for (int mt = 0; mt < 4; mt++) {
        uint32_t af[2][4];
        #pragma unroll
        for (int kd = 0; kd < 2; kd++) {
            uint4 v = __ldg(qf + (mt*2 + kd)*32);
            af[kd][0]=v.x; af[kd][1]=v.y; af[kd][2]=v.z; af[kd][3]=v.w;
        }
        float s[8][4];
        #pragma unroll
        for (int nt = 0; nt < 8; nt++)
            #pragma unroll
            for (int j = 0; j < 4; j++) s[nt][j] = 0.f;

        // QK^T in log2 domain (Q pre-scaled by SCALE*log2e)
        #pragma unroll
        for (int np = 0; np < 4; np++) {
            uint32_t kb[2][4];
            int row = np*16 + brow;
            int key = (row >> 1) & 3;
            #pragma unroll
            for (int ch = 0; ch < 2; ch++) {
                int chunk = ch*2 + bch;
                ldmx4(kb[ch], Kt + row*64 + ((chunk ^ key)*16));
            }
            float* s0 = s[2*np]; float* s1 = s[2*np+1];
            mma16816(s0, af[0], kb[0]+0); mma16816(s1, af[0], kb[0]+2);
            mma16816(s0, af[1], kb[1]+0); mma16816(s1, af[1], kb[1]+2);
        }

        // softmax (no max-pass: scores bounded); p = exp2(s + bias2)
        float den0 = 0.f, den1 = 0.f;
        #pragma unroll
        for (int nt = 0; nt < 7; nt++) {
            float4 t = __ldg(bf + (mt*7 + nt)*32);
            s[nt][0] = exp2f(s[nt][0] + t.x); den0 += s[nt][0];
            s[nt][1] = exp2f(s[nt][1] + t.y); den0 += s[nt][1];
            s[nt][2] = exp2f(s[nt][2] + t.z); den1 += s[nt][2];
            s[nt][3] = exp2f(s[nt][3] + t.w); den1 += s[nt][3];
        }
        den0 += __shfl_xor_sync(0xFFFFFFFF, den0, 1);
        den0 += __shfl_xor_sync(0xFFFFFFFF, den0, 2);
        den1 += __shfl_xor_sync(0xFFFFFFFF, den1, 1);
        den1 += __shfl_xor_sync(0xFFFFFFFF, den1, 2);
        float rinv0 = 1.f / den0, rinv1 = 1.f / den1;

        // P -> A fragments (fp16, packed cvt)
        uint32_t ph[4][4];
        #pragma unroll
        for (int ks = 0; ks < 4; ks++) {
            #pragma unroll
            for (int half_ = 0; half_ < 2; half_++) {
                int nt = 2*ks + half_;
                if (nt < 7) {
                    ph[ks][half_*2+0] = pk2f(s[nt][0], s[nt][1]);
                    ph[ks][half_*2+1] = pk2f(s[nt][2], s[nt][3]);
                } else {
                    ph[ks][half_*2] = 0; ph[ks][half_*2+1] = 0;
                }
            }
        }

        // before first PV, make sure V staging landed
        if (mt == 0) { CP_WAIT0(); __syncthreads(); }

        // PV: p x v, V via ldmatrix.trans from tok-major tiles
        float o[4][4];
        #pragma unroll
        for (int nt = 0; nt < 4; nt++)
            #pragma unroll
            for (int j = 0; j < 4; j++) o[nt][j] = 0.f;
        #pragma unroll
        for (int ks = 0; ks < 4; ks++) {
            int row = ks*16 + vrow;
            int key = (row >> 1) & 3;
            #pragma unroll
            for (int nh = 0; nh < 2; nh++) {
                uint32_t vh[4];
                int chunk = nh*2 + vch;
                ldmx4t(vh, Vt + row*64 + ((chunk ^ key)*16));
                mma16816(o[2*nh+0], ph[ks], vh+0);
                mma16816(o[2*nh+1], ph[ks], vh+2);
            }
        }

        // store to g_A2 (fp16, [t][256]), packed cvt
        int r0 = mt*16 + lr, r1 = r0 + 8;
        if (r0 < 49) {
            __half* dst = g_A2 + ((size_t)b*NTOK + r0)*KD;
            #pragma unroll
            for (int nt = 0; nt < 4; nt++) {
                int gc = h*HDIM + nt*8 + lc2;
                *(uint32_t*)(dst + gc) = pk2f(o[nt][0]*rinv0, o[nt][1]*rinv0);
            }
        }
        if (r1 < 49) {
            __half* dst = g_A2 + ((size_t)b*NTOK + r1)*KD;
            #pragma unroll
            for (int nt = 0; nt < 4; nt++) {
                int gc = h*HDIM + nt*8 + lc2;
                *(uint32_t*)(dst + gc) = pk2f(o[nt][2]*rinv1, o[nt][3]*rinv1);
            }
        }
    }
}

// ---------------- launch ----------------
extern "C" void kernel_launch(void* const* d_in, const int* in_sizes, int n_in,
                              void* d_out, int out_size)
{
    const float* x      = (const float*)d_in[0];
    const float* qg     = (const float*)d_in[1];
    const float* qkv_w  = (const float*)d_in[2];
    const float* qkv_b  = (const float*)d_in[3];
    const float* proj_w = (const float*)d_in[4];
    const float* proj_b = (const float*)d_in[5];
    const float* rbt    = (const float*)d_in[6];
    float* out = (float*)d_out;
    (void)in_sizes; (void)n_in; (void)out_size;

    cudaFuncSetAttribute(gemm_k<512>, cudaFuncAttributeMaxDynamicSharedMemorySize, GSMEM);
    cudaFuncSetAttribute(gemm_k<256>, cudaFuncAttributeMaxDynamicSharedMemorySize, GSMEM);
    cudaFuncSetAttribute(attn_k,      cudaFuncAttributeMaxDynamicSharedMemorySize, ASMEM);

    prep_conv<<<4096, 256>>>(qkv_w, proj_w, rbt, qg, x);
    {
        dim3 g1(4, TOKS/128);
        gemm_k<512><<<g1, 256, GSMEM>>>(qkv_b, nullptr);
    }
    attn_k<<<BWIN, 256, ASMEM>>>();
    {
        dim3 g2(2, TOKS/128);
        gemm_k<256><<<g2, 256, GSMEM>>>(proj_b, out);
    }
}

// round 17
// speedup vs baseline: 1.3883x; 1.0002x over previous
#include <cuda_runtime.h>
#include <cuda_fp16.h>
#include <cstdint>
#include <math.h>

#define NTOK   49
#define CDIM   256
#define HEADS  8
#define HDIM   32
#define BWIN   4096
#define TOKS   (BWIN*NTOK)          // 200704 = 1568 * 128
#define KD     256                  // plain fp16
#define NITER  4                    // K/64
#define SCALE  0.17677669529663688f
#define LOG2E  1.4426950408889634f

// ---------------- scratch (device globals; no allocs) ----------------
__device__ __half g_A1[(size_t)TOKS*KD];   // fp16(x)   [t][256]
__device__ __half g_A2[(size_t)TOKS*KD];   // attn-out  [t][256]
__device__ __half g_B1[512*KD];            // fp16(qkv_w)
__device__ __half g_B2[256*KD];            // fp16(proj_w)
// K and V tiles: [win][head] 64 tok-rows x 64B (32 fp16), swizzle key (tok>>1)&3. pads stay 0.
__device__ unsigned char g_Ks[(size_t)BWIN*HEADS*4096];
__device__ unsigned char g_Vt[(size_t)BWIN*HEADS*4096];
// Q fragments: [img][head][mtile 4][kind 2][lane 32] uint4 (pre-scaled by SCALE*LOG2E)
__device__ uint4  g_Qf[64*HEADS*4*2*32];
// bias in C-fragment layout, x LOG2E, mask folded: [head][mtile 4][ntile 7][lane 32] float4
__device__ float4 g_biasF[HEADS*4*7*32];

// ---------------- helpers ----------------
__device__ __forceinline__ uint32_t smem_u32(const void* p){
    uint32_t a;
    asm("{ .reg .u64 t; cvta.to.shared.u64 t, %1; cvt.u32.u64 %0, t; }" : "=r"(a) : "l"(p));
    return a;
}
__device__ __forceinline__ void cp_async16(uint32_t dst, const void* src){
    asm volatile("cp.async.cg.shared.global [%0], [%1], 16;" :: "r"(dst), "l"(src));
}
#define CP_COMMIT() asm volatile("cp.async.commit_group;")
#define CP_WAIT1()  asm volatile("cp.async.wait_group 1;")
#define CP_WAIT0()  asm volatile("cp.async.wait_group 0;")

__device__ __forceinline__ void ldmx4(uint32_t* r, uint32_t addr){
    asm volatile("ldmatrix.sync.aligned.m8n8.x4.shared.b16 {%0,%1,%2,%3}, [%4];"
        : "=r"(r[0]), "=r"(r[1]), "=r"(r[2]), "=r"(r[3]) : "r"(addr));
}
__device__ __forceinline__ void ldmx4t(uint32_t* r, uint32_t addr){
    asm volatile("ldmatrix.sync.aligned.m8n8.x4.trans.shared.b16 {%0,%1,%2,%3}, [%4];"
        : "=r"(r[0]), "=r"(r[1]), "=r"(r[2]), "=r"(r[3]) : "r"(addr));
}
__device__ __forceinline__ void mma16816(float* c, const uint32_t* a, const uint32_t* b){
    asm volatile("mma.sync.aligned.m16n8k16.row.col.f32.f16.f16.f32 "
        "{%0,%1,%2,%3}, {%4,%5,%6,%7}, {%8,%9}, {%0,%1,%2,%3};"
        : "+f"(c[0]), "+f"(c[1]), "+f"(c[2]), "+f"(c[3])
        : "r"(a[0]), "r"(a[1]), "r"(a[2]), "r"(a[3]), "r"(b[0]), "r"(b[1]));
}
__device__ __forceinline__ uint32_t pk2f(float a, float b){
    __half2 h = __floats2half2_rn(a, b);
    return *reinterpret_cast<uint32_t*>(&h);
}
__device__ __forceinline__ float ex2a(float x){
    float r; asm("ex2.approx.f32 %0, %1;" : "=f"(r) : "f"(x)); return r;
}
__device__ __forceinline__ float rcpa(float x){
    float r; asm("rcp.approx.f32 %0, %1;" : "=f"(r) : "f"(x)); return r;
}
__device__ __forceinline__ int rpi(int r, int c){
    int ai = r/7, aj = r%7, bi = c/7, bj = c%7;
    return (ai - bi + 6)*13 + (aj - bj + 6);
}

// ------- prep (weights, bias, Q frags) + conv_x merged, grid 4096x256 -------
__global__ void prep_conv(const float* __restrict__ qkv_w,
                          const float* __restrict__ proj_w,
                          const float* __restrict__ rbt,
                          const float* __restrict__ qg,
                          const float* __restrict__ x)
{
    int idx = blockIdx.x * 256 + threadIdx.x;
    if (idx < 512*256) g_B1[idx] = __float2half_rn(qkv_w[idx]);
    if (idx < 256*256) g_B2[idx] = __float2half_rn(proj_w[idx]);
    if (idx < HEADS*4*7*32) {
        int lane = idx & 31;
        int nt = (idx >> 5) % 7;
        int mt = (idx >> 5) / 7 % 4;
        int h  = idx / (32*7*4);
        int r0 = mt*16 + (lane>>2), r1 = r0 + 8;
        int c0 = nt*8 + 2*(lane&3), c1 = c0 + 1;
        float4 v;
        v.x = (r0 < 49 && c0 < 49) ? rbt[rpi(r0,c0)*HEADS + h]*LOG2E : -1e30f;
        v.y = (r0 < 49 && c1 < 49) ? rbt[rpi(r0,c1)*HEADS + h]*LOG2E : -1e30f;
        v.z = (r1 < 49 && c0 < 49) ? rbt[rpi(r1,c0)*HEADS + h]*LOG2E : -1e30f;
        v.w = (r1 < 49 && c1 < 49) ? rbt[rpi(r1,c1)*HEADS + h]*LOG2E : -1e30f;
        g_biasF[idx] = v;
    }
    if (idx < 64*HEADS*4*2*32) {   // Q fragments, pre-scaled by SCALE*LOG2E
        int lane = idx & 31;
        int kind = (idx >> 5) & 1;
        int mt   = (idx >> 6) & 3;
        int h    = (idx >> 8) & 7;
        int img  = idx >> 11;
        int r = mt*16 + (lane>>2);
        int c2 = 2*(lane&3);
        int db = kind * 16;
        const float qs = SCALE * LOG2E;
        auto qget = [&](int rr, int d) -> float {
            if (rr >= 49) return 0.f;
            return qg[(((size_t)img*HEADS + h)*NTOK + rr)*HDIM + d] * qs;
        };
        uint4 o;
        o.x = pk2f(qget(r,   db+c2),   qget(r,   db+c2+1));
        o.y = pk2f(qget(r+8, db+c2),   qget(r+8, db+c2+1));
        o.z = pk2f(qget(r,   db+c2+8), qget(r,   db+c2+9));
        o.w = pk2f(qget(r+8, db+c2+8), qget(r+8, db+c2+9));
        g_Qf[idx] = o;
    }
    // conv_x: grid-stride over TOKS*64 float4s
    {
        const float4* x4 = (const float4*)x;
        int stride = gridDim.x * 256;
        for (int i = idx; i < TOKS*64; i += stride) {
            float4 v = __ldg(x4 + i);
            *(uint2*)(g_A1 + (size_t)i*4) = make_uint2(pk2f(v.x, v.y), pk2f(v.z, v.w));
        }
    }
}

// ------- mma.sync fp16 GEMM, B-resident: C[128,128] per CTA, K=256 ---------
// SMEM: [0,64K) B full tile (4 k-chunks x 16KB) ; [64K, 64K+3*16K) A stages
#define GA_OFF 65536
#define GSMEM  (65536 + 3*16384)   // 112 KB

template<int NOUT>
__global__ void __launch_bounds__(256, 2)
gemm_k(const float* __restrict__ bias, float* __restrict__ extC)
{
    extern __shared__ char sm[];
    const __half* Ag = (NOUT == 512) ? g_A1 : g_A2;
    const __half* Bg = (NOUT == 512) ? g_B1 : g_B2;

    const int tid = threadIdx.x;
    const int n0 = blockIdx.x * 128;
    const int m0 = blockIdx.y * 128;
    const uint32_t sb = smem_u32(sm);

    // B: load the whole 128x256 tile once (64KB, 4096 16B chunks)
    {
        const char* Bbase = (const char*)Bg + (size_t)n0*KD*2;
        #pragma unroll
        for (int u = 0; u < 16; u++) {
            int idx = tid + u*256;          // 0..4095
            int kc = idx >> 10;             // k-chunk 0..3
            int rem = idx & 1023;
            int r = rem >> 3, c16 = rem & 7;
            uint32_t dst = (uint32_t)(kc*16384 + r*128 + ((c16 ^ (r & 7))*16));
            cp_async16(sb + dst, Bbase + (size_t)r*(KD*2) + kc*128 + c16*16);
        }
        CP_COMMIT();
    }

    auto load_a = [&](int i, int s){
        const char* Abase = (const char*)Ag + ((size_t)m0*KD + (size_t)i*64)*2;
        uint32_t sa = sb + GA_OFF + s*16384;
        #pragma unroll
        for (int u = 0; u < 4; u++) {
            int idx = tid + u*256;
            int r = idx >> 3, c16 = idx & 7;
            uint32_t dst = (uint32_t)(r*128 + ((c16 ^ (r & 7))*16));
            cp_async16(sa + dst, Abase + (size_t)r*(KD*2) + c16*16);
        }
        CP_COMMIT();
    };

    const int w = tid >> 5, lane = tid & 31;
    const int wm = w >> 1, wn = w & 1;
    const int aRow = wm*32 + (lane & 15);
    const int aC16 = (lane >> 4);
    const int bRow = wn*64 + (lane & 7) + ((lane >> 4) << 3);
    const int bC16 = (lane >> 3) & 1;
    const int lc2 = 2*(lane & 3);

    float acc[2][8][4];
    #pragma unroll
    for (int mt = 0; mt < 2; mt++)
        #pragma unroll
        for (int nt = 0; nt < 8; nt++)
            #pragma unroll
            for (int q = 0; q < 4; q++) acc[mt][nt][q] = 0.f;

    load_a(0, 0);
    load_a(1, 1);
    int s = 0;
    for (int i = 0; i < NITER; i++) {
        // pending groups: i=0:{B,A0,A1} wait1->B,A0 ; i=1:{A1,A2} wait1->A1 ; ...
        if (i < NITER-1) { CP_WAIT1(); } else { CP_WAIT0(); }
        __syncthreads();
        if (i + 2 < NITER) {
            int s2 = s + 2; if (s2 >= 3) s2 -= 3;
            load_a(i + 2, s2);
        }
        const uint32_t sa  = sb + GA_OFF + s*16384;
        const uint32_t sbB = sb + i*16384;          // resident B, k-chunk i
        uint32_t af[4][2][4];
        #pragma unroll
        for (int kk = 0; kk < 4; kk++)
            #pragma unroll
            for (int mt = 0; mt < 2; mt++) {
                int r = aRow + mt*16, c = kk*2 + aC16;
                ldmx4(af[kk][mt], sa + r*128 + ((c ^ (r & 7))*16));
            }
        #pragma unroll
        for (int kk = 0; kk < 4; kk++) {
            #pragma unroll
            for (int np = 0; np < 4; np++) {
                uint32_t bf[4];
                int r = bRow + np*16, c = kk*2 + bC16;
                ldmx4(bf, sbB + r*128 + ((c ^ (r & 7))*16));
                #pragma unroll
                for (int mt = 0; mt < 2; mt++) {
                    mma16816(acc[mt][np*2+0], af[kk][mt], bf+0);
                    mma16816(acc[mt][np*2+1], af[kk][mt], bf+2);
                }
            }
        }
        if (++s >= 3) s -= 3;
    }

    if (NOUT == 256) {
        #pragma unroll
        for (int nt = 0; nt < 8; nt++) {
            int col = n0 + wn*64 + nt*8 + lc2;
            float bx = __ldg(bias + col), by = __ldg(bias + col + 1);
            #pragma unroll
            for (int mt = 0; mt < 2; mt++) {
                int row = m0 + wm*32 + mt*16 + (lane >> 2);
                float2 v0 = make_float2(acc[mt][nt][0] + bx, acc[mt][nt][1] + by);
                float2 v1 = make_float2(acc[mt][nt][2] + bx, acc[mt][nt][3] + by);
                *(float2*)(extC + (size_t)row*NOUT + col)       = v0;
                *(float2*)(extC + (size_t)(row+8)*NOUT + col)   = v1;
            }
        }
    } else {
        // unified K/V epilogue: both hi-only tok-major 64B-row tiles, same swizzle
        const bool isK = (n0 + wn*64) < 256;
        char* arr = isK ? (char*)g_Ks : (char*)g_Vt;
        #pragma unroll
        for (int mt = 0; mt < 2; mt++) {
            int rowb = m0 + wm*32 + mt*16 + (lane >> 2);
            #pragma unroll
            for (int rr = 0; rr < 2; rr++) {
                int r = rowb + rr*8;
                int win = r / 49, tok = r - win*49;
                int key = (tok >> 1) & 3;
                char* base = arr + (size_t)win*(HEADS*4096) + (size_t)tok*64;
                #pragma unroll
                for (int nt = 0; nt < 8; nt++) {
                    int gc = n0 + wn*64 + nt*8 + lc2;
                    float v0 = acc[mt][nt][rr*2]   + __ldg(bias + gc);
                    float v1 = acc[mt][nt][rr*2+1] + __ldg(bias + gc + 1);
                    int c = gc & 255, head = c >> 5, d = c & 31;
                    char* tb = base + head*4096;
                    int chunk = d >> 3, inb = (2*d) & 15;
                    *(uint32_t*)(tb + ((chunk ^ key)*16) + inb) = pk2f(v0, v1);
                }
            }
        }
    }
}

// ---------------- tensor-core attention (fp16, ex2 softmax, no max-pass) ----
#define ASMEM (32768 + 32768)   // K 32KB + V 32KB = 64KB
__global__ void __launch_bounds__(256, 3)
attn_k()
{
    extern __shared__ char sm[];
    const int tid = threadIdx.x, b = blockIdx.x;
    const uint32_t sb = smem_u32(sm);

    {   // zero-fill pad rows 49..63 of every head tile (K and V buffers)
        for (int u = tid; u < 960; u += 256) {
            int buf = u / 480, i = u - buf*480;
            int head = i / 60, rem = i - head*60;
            uint32_t off = (uint32_t)(buf*32768 + head*4096 + (49 + (rem>>2))*64 + (rem&3)*16);
            *(uint4*)(sm + off) = make_uint4(0,0,0,0);
        }
        // stage K rows 0..48 (group 0), then V rows 0..48 (group 1)
        const char* srcK = (const char*)g_Ks + (size_t)b*32768;
        const char* srcV = (const char*)g_Vt + (size_t)b*32768;
        #pragma unroll
        for (int u = 0; u < 7; u++) {
            int i = tid + u*256;
            if (i < 1568) {
                int head = i / 196, rem = i - head*196;
                uint32_t off = (uint32_t)(head*4096 + (rem>>2)*64 + (rem&3)*16);
                cp_async16(sb + off, srcK + off);
            }
        }
        CP_COMMIT();
        #pragma unroll
        for (int u = 0; u < 7; u++) {
            int i = tid + u*256;
            if (i < 1568) {
                int head = i / 196, rem = i - head*196;
                uint32_t off = (uint32_t)(head*4096 + (rem>>2)*64 + (rem&3)*16);
                cp_async16(sb + 32768 + off, srcV + off);
            }
        }
        CP_COMMIT();
        CP_WAIT1();   // K arrived; V still in flight
    }
    __syncthreads();

    const int h = tid >> 5, lane = tid & 31;
    const int img = b >> 6;
    const uint32_t Kt = sb + h*4096;
    const uint32_t Vt = sb + 32768 + h*4096;
    const int lr = lane >> 2, lc2 = 2*(lane & 3);
    const int brow = (lane & 7) + ((lane >> 4) << 3);
    const int bch  = (lane >> 3) & 1;
    const int vrow = lane & 15;
    const int vch  = lane >> 4;

    const uint4*  qf = g_Qf    + ((size_t)(img*HEADS + h)*8)*32 + lane;
    const float4* bf = g_biasF + ((size_t)h*4*7)*32 + lane;

    for (int mt = 0; mt < 4; mt++) {
        uint32_t af[2][4];
        #pragma unroll
        for (int kd = 0; kd < 2; kd++) {
            uint4 v = __ldg(qf + (mt*2 + kd)*32);
            af[kd][0]=v.x; af[kd][1]=v.y; af[kd][2]=v.z; af[kd][3]=v.w;
        }
        float s[7][4];
        #pragma unroll
        for (int nt = 0; nt < 7; nt++)
            #pragma unroll
            for (int j = 0; j < 4; j++) s[nt][j] = 0.f;

        // QK^T in log2 domain (Q pre-scaled by SCALE*log2e).
        // ntile 7 (tokens 56-63, all pad) never computed.
        #pragma unroll
        for (int np = 0; np < 4; np++) {
            uint32_t kb[2][4];
            int row = np*16 + brow;
            int key = (row >> 1) & 3;
            #pragma unroll
            for (int ch = 0; ch < 2; ch++) {
                int chunk = ch*2 + bch;
                ldmx4(kb[ch], Kt + row*64 + ((chunk ^ key)*16));
            }
            float* s0 = s[2*np];
            mma16816(s0, af[0], kb[0]+0);
            mma16816(s0, af[1], kb[1]+0);
            if (np < 3) {
                float* s1 = s[2*np+1];
                mma16816(s1, af[0], kb[0]+2);
                mma16816(s1, af[1], kb[1]+2);
            }
        }

        // softmax (no max-pass: scores bounded); p = ex2(s + bias2)
        float den0 = 0.f, den1 = 0.f;
        #pragma unroll
        for (int nt = 0; nt < 7; nt++) {
            float4 t = __ldg(bf + (mt*7 + nt)*32);
            s[nt][0] = ex2a(s[nt][0] + t.x); den0 += s[nt][0];
            s[nt][1] = ex2a(s[nt][1] + t.y); den0 += s[nt][1];
            s[nt][2] = ex2a(s[nt][2] + t.z); den1 += s[nt][2];
            s[nt][3] = ex2a(s[nt][3] + t.w); den1 += s[nt][3];
        }
        den0 += __shfl_xor_sync(0xFFFFFFFF, den0, 1);
        den0 += __shfl_xor_sync(0xFFFFFFFF, den0, 2);
        den1 += __shfl_xor_sync(0xFFFFFFFF, den1, 1);
        den1 += __shfl_xor_sync(0xFFFFFFFF, den1, 2);
        float rinv0 = rcpa(den0), rinv1 = rcpa(den1);

        // P -> A fragments (fp16, packed cvt)
        uint32_t ph[4][4];
        #pragma unroll
        for (int ks = 0; ks < 4; ks++) {
            #pragma unroll
            for (int half_ = 0; half_ < 2; half_++) {
                int nt = 2*ks + half_;
                if (nt < 7) {
                    ph[ks][half_*2+0] = pk2f(s[nt][0], s[nt][1]);
                    ph[ks][half_*2+1] = pk2f(s[nt][2], s[nt][3]);
                } else {
                    ph[ks][half_*2] = 0; ph[ks][half_*2+1] = 0;
                }
            }
        }

        // before first PV, make sure V staging landed
        if (mt == 0) { CP_WAIT0(); __syncthreads(); }

        // PV: p x v, V via ldmatrix.trans from tok-major tiles
        float o[4][4];
        #pragma unroll
        for (int nt = 0; nt < 4; nt++)
            #pragma unroll
            for (int j = 0; j < 4; j++) o[nt][j] = 0.f;
        #pragma unroll
        for (int ks = 0; ks < 4; ks++) {
            int row = ks*16 + vrow;
            int key = (row >> 1) & 3;
            #pragma unroll
            for (int nh = 0; nh < 2; nh++) {
                uint32_t vh[4];
                int chunk = nh*2 + vch;
                ldmx4t(vh, Vt + row*64 + ((chunk ^ key)*16));
                mma16816(o[2*nh+0], ph[ks], vh+0);
                mma16816(o[2*nh+1], ph[ks], vh+2);
            }
        }

        // store to g_A2 (fp16, [t][256]), packed cvt
        int r0 = mt*16 + lr, r1 = r0 + 8;
        if (r0 < 49) {
            __half* dst = g_A2 + ((size_t)b*NTOK + r0)*KD;
            #pragma unroll
            for (int nt = 0; nt < 4; nt++) {
                int gc = h*HDIM + nt*8 + lc2;
                *(uint32_t*)(dst + gc) = pk2f(o[nt][0]*rinv0, o[nt][1]*rinv0);
            }
        }
        if (r1 < 49) {
            __half* dst = g_A2 + ((size_t)b*NTOK + r1)*KD;
            #pragma unroll
            for (int nt = 0; nt < 4; nt++) {
                int gc = h*HDIM + nt*8 + lc2;
                *(uint32_t*)(dst + gc) = pk2f(o[nt][2]*rinv1, o[nt][3]*rinv1);
            }
        }
    }
}

// ---------------- launch ----------------
extern "C" void kernel_launch(void* const* d_in, const int* in_sizes, int n_in,
                              void* d_out, int out_size)
{
    const float* x      = (const float*)d_in[0];
    const float* qg     = (const float*)d_in[1];
    const float* qkv_w  = (const float*)d_in[2];
    const float* qkv_b  = (const float*)d_in[3];
    const float* proj_w = (const float*)d_in[4];
    const float* proj_b = (const float*)d_in[5];
    const float* rbt    = (const float*)d_in[6];
    float* out = (float*)d_out;
    (void)in_sizes; (void)n_in; (void)out_size;

    cudaFuncSetAttribute(gemm_k<512>, cudaFuncAttributeMaxDynamicSharedMemorySize, GSMEM);
    cudaFuncSetAttribute(gemm_k<256>, cudaFuncAttributeMaxDynamicSharedMemorySize, GSMEM);
    cudaFuncSetAttribute(attn_k,      cudaFuncAttributeMaxDynamicSharedMemorySize, ASMEM);

    prep_conv<<<4096, 256>>>(qkv_w, proj_w, rbt, qg, x);
    {
        dim3 g1(4, TOKS/128);
        gemm_k<512><<<g1, 256, GSMEM>>>(qkv_b, nullptr);
    }
    attn_k<<<BWIN, 256, ASMEM>>>();
    {
        dim3 g2(2, TOKS/128);
        gemm_k<256><<<g2, 256, GSMEM>>>(proj_b, out);
    }
}